// round 3
// baseline (speedup 1.0000x reference)
#include <cuda_runtime.h>

// Fold: x (B=8, C=32, K1=8, K2=8, L=4096) -> out (B, C, H=260, W=260)
// kernel (8,8), stride (4,4), n = 64.
// Gather with quad-of-ow vectorization; each thread now computes TWO
// independent output rows (oh, oh+130) for the same quad q, doubling MLP
// (32 front-batched LDGs) and halving per-output index math.

namespace {
constexpr int B = 8;
constexpr int C = 32;
constexpr int K = 8;
constexpr int N = 64;               // patch grid
constexpr int L = N * N;            // 4096
constexpr int H = 260;
constexpr int W = 260;
constexpr int QW = W / 4;           // 65 quads per row
constexpr int HH = H / 2;           // 130 row-pairs (oh, oh+130)
constexpr int TOTAL_T = B * C * HH * QW;  // 2,163,200 threads
}

struct RowAcc {
    float v[4];
};

__device__ __forceinline__ void gather_row(
    const float* __restrict__ xb, int oh, int q, RowAcc& acc) {
    int di0 = oh & 3;
    int di1 = di0 + 4;
    int i0  = oh >> 2;          // row for di0 (may be 64 == invalid)
    int i1  = i0 - 1;           // row for di1 (may be -1)

    bool vi0 = i0 < N;
    bool vi1 = i1 >= 0;
    bool vj0 = q < N;           // q may be 64 on last quad
    bool vj1 = q >= 1;

    int row0 = i0 * N;
    int row1 = i1 * N;

    bool v00 = vi0 && vj0, v01 = vi0 && vj1;
    bool v10 = vi1 && vj0, v11 = vi1 && vj1;

    float a[4], b[4], c[4], d[4];
#pragma unroll
    for (int r = 0; r < 4; r++) {
        a[r] = v00 ? xb[(di0 * K + r) * L + row0 + q] : 0.f;
        b[r] = v01 ? xb[(di0 * K + r + 4) * L + row0 + q - 1] : 0.f;
        c[r] = v10 ? xb[(di1 * K + r) * L + row1 + q] : 0.f;
        d[r] = v11 ? xb[(di1 * K + r + 4) * L + row1 + q - 1] : 0.f;
    }
#pragma unroll
    for (int r = 0; r < 4; r++)
        acc.v[r] = (a[r] + b[r]) + (c[r] + d[r]);
}

__global__ __launch_bounds__(256) void fold_quad2_kernel(
    const float* __restrict__ x, float* __restrict__ out) {
    int tid = blockIdx.x * blockDim.x + threadIdx.x;
    if (tid >= TOTAL_T) return;

    int q   = tid % QW;         // 0..64
    int t   = tid / QW;
    int ohh = t % HH;           // 0..129
    int bc  = t / HH;           // 0..255

    const float* __restrict__ xb = x + (long long)bc * (K * K * L);

    int oh0 = ohh;
    int oh1 = ohh + HH;         // independent second row

    RowAcc r0, r1;
    gather_row(xb, oh0, q, r0);
    gather_row(xb, oh1, q, r1);

    float* ob = out + (long long)bc * (H * W);
    float4* p0 = (float4*)(ob + oh0 * W);
    float4* p1 = (float4*)(ob + oh1 * W);
    p0[q] = make_float4(r0.v[0], r0.v[1], r0.v[2], r0.v[3]);
    p1[q] = make_float4(r1.v[0], r1.v[1], r1.v[2], r1.v[3]);
}

extern "C" void kernel_launch(void* const* d_in, const int* in_sizes, int n_in,
                              void* d_out, int out_size) {
    const float* x = (const float*)d_in[0];
    float* out = (float*)d_out;
    int threads = 256;
    int blocks = (TOTAL_T + threads - 1) / threads;  // 8450
    fold_quad2_kernel<<<blocks, threads>>>(x, out);
}

// round 4
// speedup vs baseline: 1.0474x; 1.0474x over previous
#include <cuda_runtime.h>

// Fold: x (B=8, C=32, K1=8, K2=8, L=4096) -> out (B, C, H=260, W=260)
// kernel (8,8), stride (4,4), n = 64.
// R2 quad-gather shape (proven best) + ld.global.nc.L2::256B on the input
// stream: every 256B plane-row is fully consumed, so 256B L2 promotion
// halves DRAM request count on the read side with zero overfetch.

namespace {
constexpr int B = 8;
constexpr int C = 32;
constexpr int K = 8;
constexpr int N = 64;               // patch grid
constexpr int L = N * N;            // 4096
constexpr int H = 260;
constexpr int W = 260;
constexpr int QW = W / 4;           // 65 quads per row
constexpr int TOTAL_Q = B * C * H * QW;  // 4,326,400 (= 16900 * 256 exactly)
}

__device__ __forceinline__ float ldg_256(const float* p) {
    float v;
    asm volatile("ld.global.nc.L2::256B.f32 %0, [%1];" : "=f"(v) : "l"(p));
    return v;
}

__global__ __launch_bounds__(256) void fold_quad_l2_kernel(
    const float* __restrict__ x, float* __restrict__ out) {
    int tid = blockIdx.x * blockDim.x + threadIdx.x;   // no tail: grid exact

    int q  = tid % QW;          // 0..64
    int t  = tid / QW;
    int oh = t % H;             // 0..259
    int bc = t / H;             // 0..255

    const float* __restrict__ xb = x + (long long)bc * (K * K * L);

    int di0 = oh & 3;
    int di1 = di0 + 4;
    int i0  = oh >> 2;          // row for di0 (may be 64 == invalid)
    int i1  = i0 - 1;           // row for di1 (may be -1)

    bool vi0 = i0 < N;
    bool vi1 = i1 >= 0;
    bool vj0 = q < N;           // q may be 64 on last quad
    bool vj1 = q >= 1;

    int row0 = i0 * N;
    int row1 = i1 * N;

    bool v00 = vi0 && vj0, v01 = vi0 && vj1;
    bool v10 = vi1 && vj0, v11 = vi1 && vj1;

    float a[4], b[4], c[4], d[4];
#pragma unroll
    for (int r = 0; r < 4; r++) {
        a[r] = v00 ? ldg_256(xb + (di0 * K + r) * L + row0 + q) : 0.f;
        b[r] = v01 ? ldg_256(xb + (di0 * K + r + 4) * L + row0 + q - 1) : 0.f;
        c[r] = v10 ? ldg_256(xb + (di1 * K + r) * L + row1 + q) : 0.f;
        d[r] = v11 ? ldg_256(xb + (di1 * K + r + 4) * L + row1 + q - 1) : 0.f;
    }

    float4 o;
    o.x = (a[0] + b[0]) + (c[0] + d[0]);
    o.y = (a[1] + b[1]) + (c[1] + d[1]);
    o.z = (a[2] + b[2]) + (c[2] + d[2]);
    o.w = (a[3] + b[3]) + (c[3] + d[3]);

    float4* outv = (float4*)(out + (long long)bc * (H * W) + oh * W);
    outv[q] = o;
}

extern "C" void kernel_launch(void* const* d_in, const int* in_sizes, int n_in,
                              void* d_out, int out_size) {
    const float* x = (const float*)d_in[0];
    float* out = (float*)d_out;
    int threads = 256;
    int blocks = TOTAL_Q / threads;  // 16,900 exactly
    fold_quad_l2_kernel<<<blocks, threads>>>(x, out);
}